// round 3
// baseline (speedup 1.0000x reference)
#include <cuda_runtime.h>
#include <math.h>

// ---------------- problem constants ----------------
#define NB 16
#define NS 25
#define NQ 15
#define NWAY 5
#define NIMG 640            // 400 support + 240 query
#define HL 32
#define DEMB 1600           // 5*5*64
#define GATES 128           // 4*HL

// ---------------- scratch (device globals; no allocations allowed) ----------------
__device__ float g_buf1[640 * 42 * 42 * 64];   // after layer1 pool
__device__ float g_buf2[640 * 21 * 21 * 64];   // after layer2 pool
__device__ float g_buf3[640 * 10 * 10 * 64];   // after layer3 pool
__device__ float g_emb [640 * DEMB];           // embeddings (5*5*64)
__device__ float g_xwkf[640 * GATES];          // emb @ Wk_fwd + b_fwd
__device__ float g_xwkb[640 * GATES];          // emb @ Wk_bwd + b_bwd
__device__ float g_sf[NS * NB * HL];           // support fwd hiddens [s][b][32]
__device__ float g_sb[NS * NB * HL];           // support bwd hiddens [s][b][32]
__device__ float g_qf[NQ * NB * HL];           // query fwd hiddens   [q][b][32]
__device__ float g_qb[NQ * NB * HL];           // query bwd hiddens   [q][b][32]

// ---------------- fused conv3x3(SAME) + BN + ReLU + maxpool2x2 ----------------
template <int CIN, int H, int PH, bool FIRST>
__global__ void conv_bn_relu_pool(const float* __restrict__ in,
                                  const float* __restrict__ in_sup,
                                  const float* __restrict__ in_qry,
                                  const float* __restrict__ wt,    // [3][3][CIN][64]
                                  const float* __restrict__ cb,    // [64] (per-layer slice)
                                  const float* __restrict__ gm,
                                  const float* __restrict__ bt,
                                  const float* __restrict__ mn,
                                  const float* __restrict__ vr,
                                  float* __restrict__ out)         // [N][PH][PH][64]
{
    constexpr int W  = H;
    constexpr int PW = PH;
    constexpr int TSTR = 61;

    __shared__ float sIn[CIN * TSTR];

    const int tid = threadIdx.x;          // 0..255
    const int oc  = tid & 63;
    const int tt  = tid >> 6;             // 0..3
    const int tr  = tt >> 1;              // pooled row within tile (0..1)
    const int tc2 = tt & 1;               // pooled col pair (0..1)

    const int img = blockIdx.z;
    const int pr0 = blockIdx.y * 2;
    const int pc0 = blockIdx.x * 4;
    const int ir0 = 2 * pr0 - 1;          // input tile origin row (can be -1)
    const int ic0 = 2 * pc0 - 1;

    const float* base;
    if (FIRST) {
        base = (img < 400) ? (in_sup + (size_t)img * H * W * CIN)
                           : (in_qry + (size_t)(img - 400) * H * W * CIN);
    } else {
        base = in + (size_t)img * H * W * CIN;
    }

    // cooperative SMEM load, cin-fastest for coalescing
    for (int e = tid; e < CIN * 60; e += 256) {
        int cin = e % CIN;
        int rc  = e / CIN;
        int r = rc / 10, c = rc % 10;
        int gr = ir0 + r, gc = ic0 + c;
        float v = 0.f;
        if (gr >= 0 && gr < H && gc >= 0 && gc < W)
            v = __ldg(base + ((size_t)gr * W + gc) * CIN + cin);
        sIn[cin * TSTR + r * 10 + c] = v;
    }
    __syncthreads();

    float acc[2][4];
#pragma unroll
    for (int r = 0; r < 2; r++)
#pragma unroll
        for (int c = 0; c < 4; c++) acc[r][c] = 0.f;

    const int sbase = 2 * tr * 10 + 4 * tc2;

    for (int cin = 0; cin < CIN; cin++) {
        float xr[4][6];
        const float* sp = &sIn[cin * TSTR + sbase];
#pragma unroll
        for (int rr = 0; rr < 4; rr++)
#pragma unroll
            for (int cc = 0; cc < 6; cc++)
                xr[rr][cc] = sp[rr * 10 + cc];

        const float* wp = wt + cin * 64 + oc;
#pragma unroll
        for (int ky = 0; ky < 3; ky++)
#pragma unroll
            for (int kx = 0; kx < 3; kx++) {
                float wv = __ldg(wp + (ky * 3 + kx) * CIN * 64);
#pragma unroll
                for (int r = 0; r < 2; r++)
#pragma unroll
                    for (int c = 0; c < 4; c++)
                        acc[r][c] = fmaf(xr[r + ky][c + kx], wv, acc[r][c]);
            }
    }

    // BN fold: y = relu((conv + b - mean) * gamma*rsqrt(var+eps) + beta)
    const float s = __ldg(gm + oc) * rsqrtf(__ldg(vr + oc) + 1e-3f);
    const float t = (__ldg(cb + oc) - __ldg(mn + oc)) * s + __ldg(bt + oc);

    float v[2][4];
#pragma unroll
    for (int r = 0; r < 2; r++)
#pragma unroll
        for (int c = 0; c < 4; c++)
            v[r][c] = fmaxf(fmaf(acc[r][c], s, t), 0.f);

    const int pr = pr0 + tr;
#pragma unroll
    for (int j = 0; j < 2; j++) {
        const int pc = pc0 + 2 * tc2 + j;
        if (pr < PH && pc < PW) {
            float pv = fmaxf(fmaxf(v[0][2 * j], v[0][2 * j + 1]),
                             fmaxf(v[1][2 * j], v[1][2 * j + 1]));
            out[(((size_t)img * PH + pr) * PW + pc) * 64 + oc] = pv;
        }
    }
}

// ---------------- x @ Wk + bias (640 x 1600 @ 1600 x 128) ----------------
__global__ void xwk_gemm(const float* __restrict__ emb,
                         const float* __restrict__ Wk,
                         const float* __restrict__ bias,
                         float* __restrict__ outp)
{
    int idx = blockIdx.x * blockDim.x + threadIdx.x;
    if (idx >= NIMG * GATES) return;
    int u = idx & (GATES - 1);
    int n = idx >> 7;
    const float* e = emb + (size_t)n * DEMB;
    float acc = __ldg(bias + u);
#pragma unroll 4
    for (int k = 0; k < DEMB; k += 4) {
        float4 ev = *reinterpret_cast<const float4*>(e + k);
        acc = fmaf(ev.x, __ldg(Wk + (size_t)(k + 0) * GATES + u), acc);
        acc = fmaf(ev.y, __ldg(Wk + (size_t)(k + 1) * GATES + u), acc);
        acc = fmaf(ev.z, __ldg(Wk + (size_t)(k + 2) * GATES + u), acc);
        acc = fmaf(ev.w, __ldg(Wk + (size_t)(k + 3) * GATES + u), acc);
    }
    outp[idx] = acc;
}

// ---------------- LSTM chains over the BATCH axis ----------------
// Reference quirk: lax.scan runs over the batch axis (16 steps); each of the 26
// sequence positions has an independent (h, c) carried across batch elements.
// => positions are independent chains. Support positions (0..24) are
// query-independent; only position 25 (the query slot) differs per query.
//
// grid = (40, 2): blockIdx.x = chain (0..24 support pos s, 25..39 query q),
//                 blockIdx.y = direction (0 fwd over b=0..15, 1 bwd over b=15..0).
// 128 threads: thread u computes gate unit u (z = xwk + h @ Wr).
__device__ __forceinline__ float sigm(float x) { return 1.f / (1.f + expf(-x)); }

__global__ void lstm_chains(const float* __restrict__ xwkf,
                            const float* __restrict__ xwkb,
                            const float* __restrict__ Wrf,   // [32][128]
                            const float* __restrict__ Wrb,
                            float* __restrict__ sf,          // [25][16][32]
                            float* __restrict__ sb,
                            float* __restrict__ qf,          // [15][16][32]
                            float* __restrict__ qb)
{
    __shared__ float wr[HL * GATES];
    __shared__ float h[HL], c[HL], z[GATES];

    const int u     = threadIdx.x;       // 0..127
    const int chain = blockIdx.x;        // 0..39
    const int dir   = blockIdx.y;        // 0 fwd, 1 bwd

    const float* xwk = dir ? xwkb : xwkf;
    const float* Wr  = dir ? Wrb  : Wrf;
    float* outp = (chain < NS) ? (dir ? sb : sf) : (dir ? qb : qf);
    const int cpos = (chain < NS) ? chain : (chain - NS);

#pragma unroll
    for (int k = 0; k < HL; k++) wr[k * GATES + u] = Wr[k * GATES + u];
    if (u < HL) { h[u] = 0.f; c[u] = 0.f; }
    __syncthreads();

    for (int t = 0; t < NB; t++) {
        const int b = dir ? (NB - 1 - t) : t;
        const int row = (chain < NS) ? (b * NS + cpos) : (400 + b * NQ + cpos);

        float acc = __ldg(xwk + (size_t)row * GATES + u);
#pragma unroll
        for (int k = 0; k < HL; k++) acc = fmaf(h[k], wr[k * GATES + u], acc);
        z[u] = acc;
        __syncthreads();

        if (u < HL) {
            float zi = z[u];
            float zf = z[HL + u];
            float zg = z[2 * HL + u];
            float zo = z[3 * HL + u];
            float cc = sigm(zf) * c[u] + sigm(zi) * tanhf(zg);
            float hh = sigm(zo) * tanhf(cc);
            c[u] = cc; h[u] = hh;
            outp[(cpos * NB + b) * HL + u] = hh;
        }
        __syncthreads();
    }
}

// ---------------- attention readout + CE + accuracy ----------------
__global__ void readout(const float* __restrict__ sf,    // [25][16][32]
                        const float* __restrict__ sb,
                        const float* __restrict__ qf,    // [15][16][32]
                        const float* __restrict__ qb,
                        const int* __restrict__ ysup,    // [16][25]
                        const int* __restrict__ yqry,    // [16][15]
                        float* __restrict__ out)         // [17]
{
    __shared__ float ce_sm[NQ * NB];
    __shared__ float corr_sm[NQ * NB];
    const int t = threadIdx.x;   // 256

    if (t < NQ * NB) {
        const int q = t / NB, b = t % NB;
        float vf[HL], vb[HL];
#pragma unroll
        for (int j = 0; j < HL; j++) {
            vf[j] = qf[(q * NB + b) * HL + j];
            vb[j] = qb[(q * NB + b) * HL + j];
        }
        float scores[NS];
        float mx = -1e30f;
        for (int s = 0; s < NS; s++) {
            float dot = 0.f, nrm = 0.f;
#pragma unroll
            for (int j = 0; j < HL; j++) {
                float a = sf[(s * NB + b) * HL + j];
                dot = fmaf(vf[j], a, dot);
                nrm = fmaf(a, a, nrm);
            }
#pragma unroll
            for (int j = 0; j < HL; j++) {
                float a = sb[(s * NB + b) * HL + j];
                dot = fmaf(vb[j], a, dot);
                nrm = fmaf(a, a, nrm);
            }
            float sc = dot * rsqrtf(fmaxf(nrm, 1e-10f));
            scores[s] = sc;
            mx = fmaxf(mx, sc);
        }
        float sum = 0.f;
        for (int s = 0; s < NS; s++) { scores[s] = expf(scores[s] - mx); sum += scores[s]; }
        float inv = 1.f / sum;
        float preds[NWAY] = {0.f, 0.f, 0.f, 0.f, 0.f};
        for (int s = 0; s < NS; s++)
            preds[ysup[b * NS + s]] += scores[s] * inv;

        float psum = 0.f;
        for (int w = 0; w < NWAY; w++) psum += preds[w];
        const int yq = yqry[b * NQ + q];
        float pv = preds[yq] / psum;
        pv = fminf(fmaxf(pv, 1e-7f), 1.f - 1e-7f);
        ce_sm[t] = -logf(pv);

        int am = 0; float bv = preds[0];
        for (int w = 1; w < NWAY; w++) if (preds[w] > bv) { bv = preds[w]; am = w; }
        corr_sm[t] = (am == yq) ? 1.f : 0.f;
    }
    __syncthreads();
    if (t < NB) {
        float s = 0.f;
        for (int q = 0; q < NQ; q++) s += ce_sm[q * NB + t];
        out[t] = s / (float)NQ;
    }
    if (t == 16) {
        float s = 0.f;
        for (int i = 0; i < NQ * NB; i++) s += corr_sm[i];
        out[16] = s / (float)(NQ * NB);
    }
}

// ---------------- launch ----------------
extern "C" void kernel_launch(void* const* d_in, const int* in_sizes, int n_in,
                              void* d_out, int out_size)
{
    const float* xs = (const float*)d_in[0];
    const float* xq = (const float*)d_in[1];
    const int*   ys = (const int*)  d_in[2];
    const int*   yq = (const int*)  d_in[3];
    const float* w1 = (const float*)d_in[4];
    const float* w2 = (const float*)d_in[5];
    const float* w3 = (const float*)d_in[6];
    const float* w4 = (const float*)d_in[7];
    const float* cb = (const float*)d_in[8];
    const float* gm = (const float*)d_in[9];
    const float* bt = (const float*)d_in[10];
    const float* mn = (const float*)d_in[11];
    const float* vr = (const float*)d_in[12];
    const float* fk = (const float*)d_in[13];
    const float* fr = (const float*)d_in[14];
    const float* fb = (const float*)d_in[15];
    const float* bk = (const float*)d_in[16];
    const float* br = (const float*)d_in[17];
    const float* bb = (const float*)d_in[18];

    float *buf1, *buf2, *buf3, *emb, *xwkf, *xwkb, *sf, *sb, *qf, *qb;
    cudaGetSymbolAddress((void**)&buf1, g_buf1);
    cudaGetSymbolAddress((void**)&buf2, g_buf2);
    cudaGetSymbolAddress((void**)&buf3, g_buf3);
    cudaGetSymbolAddress((void**)&emb,  g_emb);
    cudaGetSymbolAddress((void**)&xwkf, g_xwkf);
    cudaGetSymbolAddress((void**)&xwkb, g_xwkb);
    cudaGetSymbolAddress((void**)&sf,   g_sf);
    cudaGetSymbolAddress((void**)&sb,   g_sb);
    cudaGetSymbolAddress((void**)&qf,   g_qf);
    cudaGetSymbolAddress((void**)&qb,   g_qb);

    // 4 conv blocks (pooled-tile grids: ceil(PH/2) rows x ceil(PW/4) cols)
    conv_bn_relu_pool<3, 84, 42, true><<<dim3(11, 21, 640), 256>>>(
        nullptr, xs, xq, w1, cb + 0,   gm + 0,   bt + 0,   mn + 0,   vr + 0,   buf1);
    conv_bn_relu_pool<64, 42, 21, false><<<dim3(6, 11, 640), 256>>>(
        buf1, nullptr, nullptr, w2, cb + 64,  gm + 64,  bt + 64,  mn + 64,  vr + 64,  buf2);
    conv_bn_relu_pool<64, 21, 10, false><<<dim3(3, 5, 640), 256>>>(
        buf2, nullptr, nullptr, w3, cb + 128, gm + 128, bt + 128, mn + 128, vr + 128, buf3);
    conv_bn_relu_pool<64, 10, 5, false><<<dim3(2, 3, 640), 256>>>(
        buf3, nullptr, nullptr, w4, cb + 192, gm + 192, bt + 192, mn + 192, vr + 192, emb);

    // x @ Wk + bias for both LSTM directions
    xwk_gemm<<<(NIMG * GATES + 255) / 256, 256>>>(emb, fk, fb, xwkf);
    xwk_gemm<<<(NIMG * GATES + 255) / 256, 256>>>(emb, bk, bb, xwkb);

    // FCE: 40 position-chains x 2 directions, recurrence over the batch axis
    lstm_chains<<<dim3(40, 2), GATES>>>(xwkf, xwkb, fr, br, sf, sb, qf, qb);

    // attention + CE + acc
    readout<<<1, 256>>>(sf, sb, qf, qb, ys, yq, (float*)d_out);
}

// round 5
// speedup vs baseline: 1.1931x; 1.1931x over previous
#include <cuda_runtime.h>
#include <math.h>

// ---------------- problem constants ----------------
#define NB 16
#define NS 25
#define NQ 15
#define NWAY 5
#define NIMG 640            // 400 support + 240 query
#define HL 32
#define DEMB 1600           // 5*5*64
#define GATES 128           // 4*HL

// ---------------- scratch (device globals; no allocations allowed) ----------------
__device__ float g_buf1[640 * 42 * 42 * 64];   // after layer1 pool
__device__ float g_buf2[640 * 21 * 21 * 64];   // after layer2 pool
__device__ float g_buf3[640 * 10 * 10 * 64];   // after layer3 pool
__device__ float g_emb [640 * DEMB];           // embeddings (5*5*64)
__device__ float g_xwkf[640 * GATES];          // emb @ Wk_fwd + b_fwd
__device__ float g_xwkb[640 * GATES];          // emb @ Wk_bwd + b_bwd
__device__ float g_sf[NS * NB * HL];           // support fwd hiddens [s][b][32]
__device__ float g_sb[NS * NB * HL];           // support bwd hiddens [s][b][32]
__device__ float g_qf[NQ * NB * HL];           // query fwd hiddens   [q][b][32]
__device__ float g_qb[NQ * NB * HL];           // query bwd hiddens   [q][b][32]

// ---------------- fused conv3x3(SAME) + BN + ReLU + maxpool2x2 ----------------
// 256 threads = 32 oc-lanes x 8 spatial tiles. Each thread computes TWO output
// channels (oc, oc+32) for one pooled row x two pooled cols (2x4 conv outputs).
// A warp shares one spatial tile -> all LDS are warp-uniform broadcasts.
// Block pooled tile: TTR rows x 2*TTC cols (TTR*TTC == 8).
template <int CIN, int H, int PH, int TTR, int TTC, bool FIRST>
__global__ void __launch_bounds__(256, 2)
conv_bn_relu_pool(const float* __restrict__ in,
                  const float* __restrict__ in_sup,
                  const float* __restrict__ in_qry,
                  const float* __restrict__ wt,    // [3][3][CIN][64]
                  const float* __restrict__ cb,    // [64] per-layer slices
                  const float* __restrict__ gm,
                  const float* __restrict__ bt,
                  const float* __restrict__ mn,
                  const float* __restrict__ vr,
                  float* __restrict__ out)         // [N][PH][PH][64]
{
    constexpr int W    = H;
    constexpr int PW   = PH;
    constexpr int ROWS = 2 * TTR + 2;            // input tile rows
    constexpr int COLS = 4 * TTC + 2;            // input tile cols
    constexpr int STRIDE = (COLS + 3) & ~3;      // pad to 4 for LDS.128 alignment

    __shared__ __align__(16) float sIn[CIN * ROWS * STRIDE];

    const int tid = threadIdx.x;                 // 0..255
    const int oc  = tid & 31;                    // lane = out-channel (and +32)
    const int tt  = tid >> 5;                    // warp = spatial tile 0..7
    const int a   = tt / TTC;                    // pooled row within block tile
    const int tcc = tt % TTC;                    // pooled col-pair within block tile

    const int img = blockIdx.z;
    const int pr0 = blockIdx.y * TTR;
    const int pc0 = blockIdx.x * (2 * TTC);
    const int ir0 = 2 * pr0 - 1;                 // input tile origin (SAME pad)
    const int ic0 = 2 * pc0 - 1;

    const float* base;
    if (FIRST) {
        base = (img < 400) ? (in_sup + (size_t)img * H * W * CIN)
                           : (in_qry + (size_t)(img - 400) * H * W * CIN);
    } else {
        base = in + (size_t)img * H * W * CIN;
    }

    // cooperative SMEM load, cin-fastest for global coalescing
    constexpr int NELEM = CIN * ROWS * COLS;
    for (int e = tid; e < NELEM; e += 256) {
        int cin = e % CIN;
        int rc  = e / CIN;
        int r = rc / COLS, c = rc % COLS;
        int gr = ir0 + r, gc = ic0 + c;
        float v = 0.f;
        if (gr >= 0 && gr < H && gc >= 0 && gc < W)
            v = __ldg(base + ((size_t)gr * W + gc) * CIN + cin);
        sIn[(cin * ROWS + r) * STRIDE + c] = v;
    }
    __syncthreads();

    float acc[2][2][4];                          // [oc-half][conv row][conv col]
#pragma unroll
    for (int h = 0; h < 2; h++)
#pragma unroll
        for (int r = 0; r < 2; r++)
#pragma unroll
            for (int c = 0; c < 4; c++) acc[h][r][c] = 0.f;

    const int sbase = 2 * a * STRIDE + 4 * tcc;  // 4-aligned by construction

    for (int cin = 0; cin < CIN; cin++) {
        // 4 rows x 6 cols of input, vectorized broadcast loads
        float xr[4][6];
        const float* sp = &sIn[cin * ROWS * STRIDE + sbase];
#pragma unroll
        for (int rr = 0; rr < 4; rr++) {
            float4 v4 = *reinterpret_cast<const float4*>(sp + rr * STRIDE);
            float2 v2 = *reinterpret_cast<const float2*>(sp + rr * STRIDE + 4);
            xr[rr][0] = v4.x; xr[rr][1] = v4.y; xr[rr][2] = v4.z; xr[rr][3] = v4.w;
            xr[rr][4] = v2.x; xr[rr][5] = v2.y;
        }

        const float* wp = wt + cin * 64 + oc;
#pragma unroll
        for (int ky = 0; ky < 3; ky++)
#pragma unroll
            for (int kx = 0; kx < 3; kx++) {
                const float* wq = wp + (ky * 3 + kx) * CIN * 64;
                float w0 = __ldg(wq);
                float w1 = __ldg(wq + 32);
#pragma unroll
                for (int r = 0; r < 2; r++)
#pragma unroll
                    for (int c = 0; c < 4; c++) {
                        float xv = xr[r + ky][c + kx];
                        acc[0][r][c] = fmaf(xv, w0, acc[0][r][c]);
                        acc[1][r][c] = fmaf(xv, w1, acc[1][r][c]);
                    }
            }
    }

    // BN fold + ReLU + 2x2 maxpool + store (both oc halves)
    const int pr = pr0 + a;
#pragma unroll
    for (int h = 0; h < 2; h++) {
        const int och = oc + 32 * h;
        const float s = __ldg(gm + och) * rsqrtf(__ldg(vr + och) + 1e-3f);
        const float t = (__ldg(cb + och) - __ldg(mn + och)) * s + __ldg(bt + och);

        float v[2][4];
#pragma unroll
        for (int r = 0; r < 2; r++)
#pragma unroll
            for (int c = 0; c < 4; c++)
                v[r][c] = fmaxf(fmaf(acc[h][r][c], s, t), 0.f);

#pragma unroll
        for (int j = 0; j < 2; j++) {
            const int pc = pc0 + 2 * tcc + j;
            if (pr < PH && pc < PW) {
                float pv = fmaxf(fmaxf(v[0][2 * j], v[0][2 * j + 1]),
                                 fmaxf(v[1][2 * j], v[1][2 * j + 1]));
                out[(((size_t)img * PH + pr) * PW + pc) * 64 + och] = pv;
            }
        }
    }
}

// ---------------- x @ Wk + bias (640 x 1600 @ 1600 x 128) ----------------
__global__ void xwk_gemm(const float* __restrict__ emb,
                         const float* __restrict__ Wk,
                         const float* __restrict__ bias,
                         float* __restrict__ outp)
{
    int idx = blockIdx.x * blockDim.x + threadIdx.x;
    if (idx >= NIMG * GATES) return;
    int u = idx & (GATES - 1);
    int n = idx >> 7;
    const float* e = emb + (size_t)n * DEMB;
    float acc = __ldg(bias + u);
#pragma unroll 4
    for (int k = 0; k < DEMB; k += 4) {
        float4 ev = *reinterpret_cast<const float4*>(e + k);
        acc = fmaf(ev.x, __ldg(Wk + (size_t)(k + 0) * GATES + u), acc);
        acc = fmaf(ev.y, __ldg(Wk + (size_t)(k + 1) * GATES + u), acc);
        acc = fmaf(ev.z, __ldg(Wk + (size_t)(k + 2) * GATES + u), acc);
        acc = fmaf(ev.w, __ldg(Wk + (size_t)(k + 3) * GATES + u), acc);
    }
    outp[idx] = acc;
}

// ---------------- LSTM chains over the BATCH axis ----------------
// lax.scan runs over the batch axis (16 steps); each of the 26 sequence
// positions is an independent (h, c) chain. Support positions (0..24) are
// query-independent; only the query slot differs per query.
__device__ __forceinline__ float sigm(float x) { return 1.f / (1.f + expf(-x)); }

__global__ void lstm_chains(const float* __restrict__ xwkf,
                            const float* __restrict__ xwkb,
                            const float* __restrict__ Wrf,   // [32][128]
                            const float* __restrict__ Wrb,
                            float* __restrict__ sf,          // [25][16][32]
                            float* __restrict__ sb,
                            float* __restrict__ qf,          // [15][16][32]
                            float* __restrict__ qb)
{
    __shared__ float wr[HL * GATES];
    __shared__ float h[HL], c[HL], z[GATES];

    const int u     = threadIdx.x;       // 0..127
    const int chain = blockIdx.x;        // 0..39
    const int dir   = blockIdx.y;        // 0 fwd, 1 bwd

    const float* xwk = dir ? xwkb : xwkf;
    const float* Wr  = dir ? Wrb  : Wrf;
    float* outp = (chain < NS) ? (dir ? sb : sf) : (dir ? qb : qf);
    const int cpos = (chain < NS) ? chain : (chain - NS);

#pragma unroll
    for (int k = 0; k < HL; k++) wr[k * GATES + u] = Wr[k * GATES + u];
    if (u < HL) { h[u] = 0.f; c[u] = 0.f; }
    __syncthreads();

    for (int t = 0; t < NB; t++) {
        const int b = dir ? (NB - 1 - t) : t;
        const int row = (chain < NS) ? (b * NS + cpos) : (400 + b * NQ + cpos);

        float acc = __ldg(xwk + (size_t)row * GATES + u);
#pragma unroll
        for (int k = 0; k < HL; k++) acc = fmaf(h[k], wr[k * GATES + u], acc);
        z[u] = acc;
        __syncthreads();

        if (u < HL) {
            float zi = z[u];
            float zf = z[HL + u];
            float zg = z[2 * HL + u];
            float zo = z[3 * HL + u];
            float cc = sigm(zf) * c[u] + sigm(zi) * tanhf(zg);
            float hh = sigm(zo) * tanhf(cc);
            c[u] = cc; h[u] = hh;
            outp[(cpos * NB + b) * HL + u] = hh;
        }
        __syncthreads();
    }
}

// ---------------- attention readout + CE + accuracy ----------------
__global__ void readout(const float* __restrict__ sf,    // [25][16][32]
                        const float* __restrict__ sb,
                        const float* __restrict__ qf,    // [15][16][32]
                        const float* __restrict__ qb,
                        const int* __restrict__ ysup,    // [16][25]
                        const int* __restrict__ yqry,    // [16][15]
                        float* __restrict__ out)         // [17]
{
    __shared__ float ce_sm[NQ * NB];
    __shared__ float corr_sm[NQ * NB];
    const int t = threadIdx.x;   // 256

    if (t < NQ * NB) {
        const int q = t / NB, b = t % NB;
        float vf[HL], vb[HL];
#pragma unroll
        for (int j = 0; j < HL; j++) {
            vf[j] = qf[(q * NB + b) * HL + j];
            vb[j] = qb[(q * NB + b) * HL + j];
        }
        float scores[NS];
        float mx = -1e30f;
        for (int s = 0; s < NS; s++) {
            float dot = 0.f, nrm = 0.f;
#pragma unroll
            for (int j = 0; j < HL; j++) {
                float a = sf[(s * NB + b) * HL + j];
                dot = fmaf(vf[j], a, dot);
                nrm = fmaf(a, a, nrm);
            }
#pragma unroll
            for (int j = 0; j < HL; j++) {
                float a = sb[(s * NB + b) * HL + j];
                dot = fmaf(vb[j], a, dot);
                nrm = fmaf(a, a, nrm);
            }
            float sc = dot * rsqrtf(fmaxf(nrm, 1e-10f));
            scores[s] = sc;
            mx = fmaxf(mx, sc);
        }
        float sum = 0.f;
        for (int s = 0; s < NS; s++) { scores[s] = expf(scores[s] - mx); sum += scores[s]; }
        float inv = 1.f / sum;
        float preds[NWAY] = {0.f, 0.f, 0.f, 0.f, 0.f};
        for (int s = 0; s < NS; s++)
            preds[ysup[b * NS + s]] += scores[s] * inv;

        float psum = 0.f;
        for (int w = 0; w < NWAY; w++) psum += preds[w];
        const int yq = yqry[b * NQ + q];
        float pv = preds[yq] / psum;
        pv = fminf(fmaxf(pv, 1e-7f), 1.f - 1e-7f);
        ce_sm[t] = -logf(pv);

        int am = 0; float bv = preds[0];
        for (int w = 1; w < NWAY; w++) if (preds[w] > bv) { bv = preds[w]; am = w; }
        corr_sm[t] = (am == yq) ? 1.f : 0.f;
    }
    __syncthreads();
    if (t < NB) {
        float s = 0.f;
        for (int q = 0; q < NQ; q++) s += ce_sm[q * NB + t];
        out[t] = s / (float)NQ;
    }
    if (t == 16) {
        float s = 0.f;
        for (int i = 0; i < NQ * NB; i++) s += corr_sm[i];
        out[16] = s / (float)(NQ * NB);
    }
}

// ---------------- launch ----------------
extern "C" void kernel_launch(void* const* d_in, const int* in_sizes, int n_in,
                              void* d_out, int out_size)
{
    const float* xs = (const float*)d_in[0];
    const float* xq = (const float*)d_in[1];
    const int*   ys = (const int*)  d_in[2];
    const int*   yq = (const int*)  d_in[3];
    const float* w1 = (const float*)d_in[4];
    const float* w2 = (const float*)d_in[5];
    const float* w3 = (const float*)d_in[6];
    const float* w4 = (const float*)d_in[7];
    const float* cb = (const float*)d_in[8];
    const float* gm = (const float*)d_in[9];
    const float* bt = (const float*)d_in[10];
    const float* mn = (const float*)d_in[11];
    const float* vr = (const float*)d_in[12];
    const float* fk = (const float*)d_in[13];
    const float* fr = (const float*)d_in[14];
    const float* fb = (const float*)d_in[15];
    const float* bk = (const float*)d_in[16];
    const float* br = (const float*)d_in[17];
    const float* bb = (const float*)d_in[18];

    float *buf1, *buf2, *buf3, *emb, *xwkf, *xwkb, *sf, *sb, *qf, *qb;
    cudaGetSymbolAddress((void**)&buf1, g_buf1);
    cudaGetSymbolAddress((void**)&buf2, g_buf2);
    cudaGetSymbolAddress((void**)&buf3, g_buf3);
    cudaGetSymbolAddress((void**)&emb,  g_emb);
    cudaGetSymbolAddress((void**)&xwkf, g_xwkf);
    cudaGetSymbolAddress((void**)&xwkb, g_xwkb);
    cudaGetSymbolAddress((void**)&sf,   g_sf);
    cudaGetSymbolAddress((void**)&sb,   g_sb);
    cudaGetSymbolAddress((void**)&qf,   g_qf);
    cudaGetSymbolAddress((void**)&qb,   g_qb);

    // layer 1: 84->42, 4x4 pooled block tile
    conv_bn_relu_pool<3, 84, 42, 4, 2, true><<<dim3(11, 11, 640), 256>>>(
        nullptr, xs, xq, w1, cb + 0,   gm + 0,   bt + 0,   mn + 0,   vr + 0,   buf1);
    // layer 2: 42->21, 2x8 pooled block tile (dominant layer, lowest waste)
    conv_bn_relu_pool<64, 42, 21, 2, 4, false><<<dim3(3, 11, 640), 256>>>(
        buf1, nullptr, nullptr, w2, cb + 64,  gm + 64,  bt + 64,  mn + 64,  vr + 64,  buf2);
    // layer 3: 21->10, 4x4 pooled block tile
    conv_bn_relu_pool<64, 21, 10, 4, 2, false><<<dim3(3, 3, 640), 256>>>(
        buf2, nullptr, nullptr, w3, cb + 128, gm + 128, bt + 128, mn + 128, vr + 128, buf3);
    // layer 4: 10->5, 2x8 pooled block tile
    conv_bn_relu_pool<64, 10, 5, 2, 4, false><<<dim3(1, 3, 640), 256>>>(
        buf3, nullptr, nullptr, w4, cb + 192, gm + 192, bt + 192, mn + 192, vr + 192, emb);

    // x @ Wk + bias for both LSTM directions
    xwk_gemm<<<(NIMG * GATES + 255) / 256, 256>>>(emb, fk, fb, xwkf);
    xwk_gemm<<<(NIMG * GATES + 255) / 256, 256>>>(emb, bk, bb, xwkb);

    // FCE: 40 position-chains x 2 directions, recurrence over the batch axis
    lstm_chains<<<dim3(40, 2), GATES>>>(xwkf, xwkb, fr, br, sf, sb, qf, qb);

    // attention + CE + acc
    readout<<<1, 256>>>(sf, sb, qf, qb, ys, yq, (float*)d_out);
}